// round 1
// baseline (speedup 1.0000x reference)
#include <cuda_runtime.h>
#include <cstdint>
#include <climits>

#define D_DIM 2048
#define TPB   256
#define EPT   8      // elements per thread: 256*8 = 2048 = one row per block

__global__ __launch_bounds__(TPB)
void mxint_softmax_kernel(const float* __restrict__ x, float* __restrict__ out)
{
    const int row  = blockIdx.x;
    const int tid  = threadIdx.x;
    const int lane = tid & 31;
    const int warp = tid >> 5;

    const float* xr   = x   + (long long)row * D_DIM + tid * EPT;
    float*       orow = out + (long long)row * D_DIM + tid * EPT;

    __shared__ int s_mexpLut[32];
    __shared__ int s_acc[16];
    __shared__ int s_warpmax[TPB / 32];
    __shared__ int s_msum;
    __shared__ unsigned char s_mout[64];

    // Per-block LUT: mexp = clip(rne(2^(k/32) * 64), ., 127). exp2f err (~2ulp)
    // is 1000x smaller than the min distance (0.0097) to any .5 boundary.
    if (tid < 32) {
        s_mexpLut[tid] = min(127, (int)rintf(exp2f(fmaf((float)tid, 0.03125f, 6.0f))));
        if (tid < 16) s_acc[tid] = 0;
    }
    __syncthreads();

    float4 v0 = *(const float4*)(xr);
    float4 v1 = *(const float4*)(xr + 4);
    float xs[EPT] = {v0.x, v0.y, v0.z, v0.w, v1.x, v1.y, v1.z, v1.w};

    int e8[EPT], me8[EPT], pmax[EPT];
    int running = -100;

    #pragma unroll
    for (int k = 0; k < EPT; k++) {
        float xv = xs[k];
        float ax = fabsf(xv);
        int e1;
        if (ax == 0.0f) {
            e1 = 0;
        } else {
            int bits = __float_as_int(ax);
            int j    = (bits >> 23) - 127;
            int m23  = bits & 0x7FFFFF;
            e1 = j + (m23 != 0);
            // Emulate float32-log2 rounding: values barely above 2^j round to j
            // when ulp(|j|)/2 > log2(1 + m23*2^-23).
            int aj = j < 0 ? -j : j;
            if ((m23 == 1 && aj >= 4) || (m23 == 2 && aj >= 8)) e1 = j;
            e1 = min(7, max(-8, e1));
        }
        // m1 = clip(rne(x * 2^(7-e1)), -128, 127)   (exact pow2 scaling)
        float scale = __int_as_float((134 - e1) << 23);   // 2^(7-e1), e1 in [-8,7]
        float m1f = fminf(127.0f, fmaxf(-128.0f, rintf(xv * scale)));
        int m1 = (int)m1f;
        // t = clip(floor(y*32), -256, 255); y*32 = m1*23*2^(e1-6) exactly
        int a = m1 * 23;
        int s = 6 - e1;                       // in [-1, 14]
        int t = (s >= 0) ? (a >> s) : (a * 2);
        t = max(-256, min(255, t));
        int n = t >> 5;                       // eexp in [-8, 7]
        int mexp = s_mexpLut[t & 31];         // in [64, 127]
        e8[k]  = n;
        me8[k] = mexp;
        running = max(running, n);
        pmax[k] = running;                    // thread-local inclusive prefix max
    }

    // Block-wide inclusive prefix max of e (associative -> parallel scan)
    int inc = running;
    #pragma unroll
    for (int o = 1; o < 32; o <<= 1) {
        int v = __shfl_up_sync(0xffffffffu, inc, o);
        if (lane >= o) inc = max(inc, v);
    }
    int excl = __shfl_up_sync(0xffffffffu, inc, 1);
    if (lane == 0) excl = -100;
    if (lane == 31) s_warpmax[warp] = inc;
    __syncthreads();

    int base = excl, bmax = -100;
    #pragma unroll
    for (int w = 0; w < TPB / 32; w++) {
        int wm = s_warpmax[w];
        if (w < warp) base = max(base, wm);
        bmax = max(bmax, wm);
    }

    // Bucket by plateau value E_i (prefix max). Bit-exact vs the sequential
    // scan: within a plateau adds are exact; cross-plateau shifts compose.
    // Merge consecutive equal-E contributions per thread to keep same-address
    // shared atomics rare (E is a prefix max -> almost always one run/thread).
    {
        int curE = max(base, pmax[0]);
        int acc  = (me8[0] << 4) >> (curE - e8[0]);
        #pragma unroll
        for (int k = 1; k < EPT; k++) {
            int E = max(base, pmax[k]);
            int c = (me8[k] << 4) >> (E - e8[k]);
            if (E == curE) acc += c;
            else { atomicAdd(&s_acc[curE + 8], acc); curE = E; acc = c; }
        }
        atomicAdd(&s_acc[curE + 8], acc);
    }
    __syncthreads();

    // Serial combine over <=16 plateau values (stop at emax!)
    if (tid == 0) {
        int accv = 0;
        #pragma unroll 1
        for (int v = -8; v <= bmax; v++) accv = (accv >> 1) + s_acc[v + 8];
        s_msum = accv;
    }
    __syncthreads();

    // Per-row division LUT: only 64 distinct mexp values.
    // IEEE float divide + floorf replicates the reference's float32 path
    // (msum < 2^24 is exact in f32).
    float msumf = (float)s_msum;
    if (tid < 64) {
        s_mout[tid] = (unsigned char)floorf((float)((tid + 64) << 8) / msumf);
    }
    __syncthreads();

    const int emax = bmax;
    float res[EPT];
    #pragma unroll
    for (int k = 0; k < EPT; k++) {
        int moi = s_mout[me8[k] - 64];     // in [0, 31]
        float r = 0.0f;
        if (moi > 0) {
            int p   = e8[k] - emax - 4;                    // qout = moi * 2^p
            int cl2 = (moi <= 1) ? 0 : (32 - __clz(moi - 1)); // ceil(log2(moi))
            int e2  = min(7, max(-8, p + cl2));
            int sh  = p + 7 - e2;                          // m2 = rne(moi * 2^sh)
            float m2f;
            if (sh >= 0) m2f = (float)(moi << sh);
            else         m2f = rintf(ldexpf((float)moi, sh));
            m2f = fminf(127.0f, m2f);                      // clip (128 -> 127 case)
            r = m2f * __int_as_float((e2 + 120) << 23);    // m2 * 2^(e2-7)
        }
        res[k] = r;
    }
    *(float4*)(orow)     = make_float4(res[0], res[1], res[2], res[3]);
    *(float4*)(orow + 4) = make_float4(res[4], res[5], res[6], res[7]);
}

extern "C" void kernel_launch(void* const* d_in, const int* in_sizes, int n_in,
                              void* d_out, int out_size)
{
    const float* x = (const float*)d_in[0];
    float* out = (float*)d_out;
    int rows = in_sizes[0] / D_DIM;
    mxint_softmax_kernel<<<rows, TPB>>>(x, out);
}

// round 3
// speedup vs baseline: 1.0375x; 1.0375x over previous
#include <cuda_runtime.h>

#define D_DIM 2048
#define TPB   256
#define EPT   8      // 256*8 = 2048 = one row per block

__global__ __launch_bounds__(TPB, 6)
void mxint_softmax_kernel(const float* __restrict__ x, float* __restrict__ out)
{
    const int tid  = threadIdx.x;
    const int lane = tid & 31;
    const int warp = tid >> 5;

    const float* xr   = x   + (size_t)blockIdx.x * D_DIM + tid * EPT;
    float*       orow = out + (size_t)blockIdx.x * D_DIM + tid * EPT;

    __shared__ int s_acc[16];
    __shared__ int s_warpmax[TPB / 32];
    __shared__ int s_lut[64];            // (7-cl2)<<8 | min(127, moi<<(7-cl2))

    // Issue loads early
    float4 v0 = *(const float4*)(xr);
    float4 v1 = *(const float4*)(xr + 4);

    // Per-lane LUT register: lut[lane] = clip(rne(2^(lane/32) * 64), 127).
    // exp2f err (~2 ulp) is ~1000x below min distance (0.0097) to .5 boundary.
    int lutreg = min(127, (int)rintf(exp2f(fmaf((float)lane, 0.03125f, 6.0f))));

    if (tid < 16) s_acc[tid] = 0;

    float xs[EPT] = {v0.x, v0.y, v0.z, v0.w, v1.x, v1.y, v1.z, v1.w};

    int e8[EPT], me8[EPT];
    int run = -100;

    #pragma unroll
    for (int k = 0; k < EPT; k++) {
        float xv = xs[k];
        int bits = __float_as_int(xv) & 0x7fffffff;
        int j    = (bits >> 23) - 127;
        int m23  = bits & 0x7FFFFF;
        int e1   = j + (m23 != 0);
        // Emulate float32-log2 rounding: values barely above 2^j round to j
        // when ulp(|j|)/2 > log2(1 + m23*2^-23).
        int aj = abs(j);
        if ((m23 == 1 && aj >= 4) || (m23 == 2 && aj >= 8)) e1 = j;
        e1 = max(-8, e1);                    // upper clamp unneeded: t saturates
        // m1 = clip(rne(x * 2^(7-e1)), -128, 127)
        float m1f = rintf(xv * __int_as_float((134 - e1) << 23));
        m1f = fminf(127.0f, fmaxf(-128.0f, m1f));
        // t = clip(floor(m1*23 * 2^(e1-6)), -256, 255) = floor(m1*46 * 2^(e1-7))
        // (m1*46 <= 5888 exact in f32; pow2 scale exact; F2I.RD exact floor)
        int t = __float2int_rd(m1f * 46.0f * __int_as_float((120 + e1) << 23));
        t = max(-256, min(255, t));
        int e  = t >> 5;                     // eexp in [-8, 7]
        int me = __shfl_sync(0xffffffffu, lutreg, t & 31);  // mexp in [64,127]
        e8[k]  = e;
        me8[k] = me;
        run = max(run, e);
    }

    // Block-wide inclusive prefix max of e over thread order
    int inc = run;
    #pragma unroll
    for (int o = 1; o < 32; o <<= 1) {
        int v = __shfl_up_sync(0xffffffffu, inc, o);
        if (lane >= o) inc = max(inc, v);
    }
    int excl = __shfl_up_sync(0xffffffffu, inc, 1);
    if (lane == 0) excl = -100;
    if (lane == 31) s_warpmax[warp] = inc;
    __syncthreads();                         // also orders s_acc init

    int base = excl, bmax = -100;
    #pragma unroll
    for (int w = 0; w < TPB / 32; w++) {
        int wm = s_warpmax[w];
        if (w < warp) base = max(base, wm);
        bmax = max(bmax, wm);
    }

    // Bucket by plateau value E_i (prefix max). Bit-exact vs sequential scan:
    // within a plateau adds are exact ints; cross-plateau shifts compose.
    {
        int run2 = -100, curE = -100, acc = 0;
        #pragma unroll
        for (int k = 0; k < EPT; k++) {
            run2 = max(run2, e8[k]);
            int E = max(base, run2);
            int c = (me8[k] << 4) >> (E - e8[k]);
            if (E != curE) {
                if (k) atomicAdd(&s_acc[curE + 8], acc);
                curE = E; acc = 0;
            }
            acc += c;
        }
        atomicAdd(&s_acc[curE + 8], acc);
    }
    __syncthreads();

    // Serial combine over <=16 plateau values (redundant in all threads;
    // s_acc reads broadcast). Stop at emax.
    int accv = 0;
    #pragma unroll 1
    for (int v = -8; v <= bmax; v++) accv = (accv >> 1) + s_acc[v + 8];

    // Per-row division LUT: 64 distinct mexp values. IEEE f32 divide + floorf
    // replicates the reference's float path (accv < 2^24 exact in f32).
    // Store packed: s7 = 7 - ceil(log2 moi), mu = min(127, moi << s7).
    if (tid < 64) {
        int moi = (int)floorf((float)((tid + 64) << 8) / (float)accv);
        int cl2 = (moi <= 1) ? 0 : (32 - __clz(moi - 1));
        int s7  = 7 - cl2;
        int mu  = min(127, moi << s7);
        s_lut[tid] = (s7 << 8) | mu;
    }
    __syncthreads();

    // Epilogue: qout = moi*2^p, p = e-emax-4, re-quantized (mxint 8/4).
    // Exact closed form (proved incl. the pow2-moi 128->127 clip and the
    // e2=-8 underflow path with rne ties-to-even):
    //   d = (p+15) - s7;  r = rne(mu * 2^min(0,d)) * 2^(max(0,d) - 15)
    const int p15c = 11 - bmax;              // p15 = e + 11 - emax
    float res[EPT];
    #pragma unroll
    for (int k = 0; k < EPT; k++) {
        int w  = s_lut[me8[k] - 64];
        int d  = e8[k] + p15c - (w >> 8);
        int dn = min(0, d);
        int dp = max(0, d);
        float m2 = rintf((float)(w & 255) * __int_as_float((dn + 127) << 23));
        res[k] = m2 * __int_as_float((dp + 112) << 23);   // 2^(dp-15)
    }
    *(float4*)(orow)     = make_float4(res[0], res[1], res[2], res[3]);
    *(float4*)(orow + 4) = make_float4(res[4], res[5], res[6], res[7]);
}

extern "C" void kernel_launch(void* const* d_in, const int* in_sizes, int n_in,
                              void* d_out, int out_size)
{
    const float* x = (const float*)d_in[0];
    float* out = (float*)d_out;
    int rows = in_sizes[0] / D_DIM;
    mxint_softmax_kernel<<<rows, TPB>>>(x, out);
}

// round 4
// speedup vs baseline: 1.3417x; 1.2933x over previous
#include <cuda_runtime.h>

#define D_DIM 2048
#define TPB   256
#define EPT   8      // 256*8 = 2048 = one row per block

__global__ __launch_bounds__(TPB, 7)
void mxint_softmax_kernel(const float* __restrict__ x, float* __restrict__ out)
{
    const int tid  = threadIdx.x;
    const int lane = tid & 31;
    const int warp = tid >> 5;

    const float* xr   = x   + (size_t)blockIdx.x * D_DIM + tid * EPT;
    float*       orow = out + (size_t)blockIdx.x * D_DIM + tid * EPT;

    __shared__ int   s_acc[32];      // buckets at [16..31] (index e'+16), zero apron [0..15]
    __shared__ int   s_warpmax[8];
    __shared__ int   s_ms7[32];      // per-idx packed (s7<<8)|mu
    __shared__ float s_res[512];     // final result keyed directly by pe

    // Issue loads early
    float4 v0 = *(const float4*)(xr);
    float4 v1 = *(const float4*)(xr + 4);

    // Per-lane LUT register: lut[lane] = clip(rne(2^(lane/32) * 64), 127).
    // exp2f err (~2 ulp) is ~1000x below min distance (0.0097) to .5 boundary.
    int lutreg  = min(127, (int)rintf(exp2f(fmaf((float)lane, 0.03125f, 6.0f))));
    int lutreg4 = lutreg << 4;       // mexp*16 for the bucket sum

    if (tid < 32) s_acc[tid] = 0;

    float xs[EPT] = {v0.x, v0.y, v0.z, v0.w, v1.x, v1.y, v1.z, v1.w};

    int pe8[EPT];
    int run = 0;                     // pe-domain running max (pe >= 0)

    #pragma unroll
    for (int k = 0; k < EPT; k++) {
        float xv = xs[k];
        int bits = __float_as_int(xv) & 0x7fffffff;
        // e1 = ceil(log2 |x|) exactly via (bits-1): m23==0 -> exponent drops.
        int e1  = ((bits - 1) >> 23) - 126;
        int m23 = bits & 0x7fffff;
        // float32-log2 rounding emulation: x barely above 2^j rounds down to j
        // when ulp(|j|)/2 > log2(1+m23*2^-23), i.e. m23=1,|j|>=4 or m23=2,|j|>=8.
        if (__builtin_expect((unsigned)(m23 - 1) < 2u, 0)) {
            int j  = e1 - 1;
            int aj = j < 0 ? -j : j;
            if (aj >= (m23 << 2)) e1 = j;
        }
        e1 = max(e1, -8);            // upper clamp unneeded: t saturates below
        // m1 = clip(rne(x * 2^(7-e1)), -128, 127); -128 unreachable except exact
        float m1f = rintf(xv * __int_as_float((134 - e1) << 23));
        m1f = fminf(m1f, 127.0f);
        // t = clip(floor(m1 * 46 * 2^(e1-7)), -256, 255)
        // 46*2^(e1-7) = 1.4375*2^(e1-2): bits = ((125+e1)<<23)|0x380000 (one IMAD)
        int t = __float2int_rd(m1f * __int_as_float(((125 + e1) << 23) | 0x00380000));
        int pe = min(max(t, -256), 255) + 256;     // pe = (e+8)*32 + idx, in [0,512)
        pe8[k] = pe;
        run = max(run, pe);
    }

    // Block-wide inclusive prefix max of pe over thread order (pe is lex (e,idx),
    // so (prefix-max pe)>>5 == prefix-max of e', which is all we use).
    int inc = run;
    #pragma unroll
    for (int o = 1; o < 32; o <<= 1) {
        int v = __shfl_up_sync(0xffffffffu, inc, o);
        if (lane >= o) inc = max(inc, v);
    }
    int excl = __shfl_up_sync(0xffffffffu, inc, 1);
    if (lane == 0) excl = 0;
    if (lane == 31) s_warpmax[warp] = inc;
    __syncthreads();                         // bar1 (also orders s_acc init)

    int base = excl, bmaxpe = 0;
    #pragma unroll
    for (int w = 0; w < 8; w++) {
        int wm = s_warpmax[w];
        if (w < warp) base = max(base, wm);
        bmaxpe = max(bmaxpe, wm);
    }

    // Bucket by plateau value E (prefix max of e'). Bit-exact vs the sequential
    // scan: within a plateau adds are exact ints; cross-plateau shifts compose.
    {
        int run2 = base, curE = -1, acc = 0;
        bool multi = false;
        #pragma unroll
        for (int k = 0; k < EPT; k++) {
            int pe = pe8[k];
            run2 = max(run2, pe);
            int Ee = run2 >> 5;              // plateau value (e'+... e-domain+8)
            int ms = __shfl_sync(0xffffffffu, lutreg4, pe & 31);
            int c  = ms >> (Ee - (pe >> 5));
            if (Ee != curE) {
                if (k) { atomicAdd(&s_acc[curE + 16], acc); multi = true; }
                curE = Ee; acc = 0;
            }
            acc += c;
        }
        // Final flush: warp-aggregate when the whole warp is one uniform plateau
        // (common case) to avoid 32-way same-address ATOMS serialization.
        int  E0  = __shfl_sync(0xffffffffu, curE, 0);
        bool uni = __all_sync(0xffffffffu, (!multi) && (curE == E0));
        if (uni) {
            int s = __reduce_add_sync(0xffffffffu, acc);
            if (lane == 0) atomicAdd(&s_acc[curE + 16], s);
        } else {
            atomicAdd(&s_acc[curE + 16], acc);
        }
    }
    __syncthreads();                         // bar2

    const int bmax = (bmaxpe >> 5) - 8;      // block max e, in [-8,7]

    // Warp 0 only: serial combine (fixed 16 steps over the zero apron), then
    // per-idx division. Lane i owns LUT index i (me already in lutreg).
    if (tid < 32) {
        const int* bp = s_acc + (bmaxpe >> 5) + 1;   // indices in [1,31]
        int accv = 0;
        #pragma unroll
        for (int k = 0; k < 16; k++) accv = (accv >> 1) + bp[k];
        // IEEE f32 divide + floorf replicates the reference's float path
        // (accv < 2^24 exact in f32). moi in [0,31].
        int moi = (int)floorf((float)(lutreg << 8) / (float)accv);
        int cl2 = (moi <= 1) ? 0 : (32 - __clz(moi - 1));
        int s7  = 7 - cl2;
        int mu  = min(127, moi << s7);       // reference's clipped mantissa
        s_ms7[lane] = (s7 << 8) | mu;
    }
    __syncthreads();                         // bar3

    // Build the 512-entry result table: entry j=(e'<<5)|idx holds the fully
    // re-quantized output for (e = e'-8, idx). Exact closed form (R3-proven,
    // incl. pow2 128->127 clip and e2=-8 underflow with rne ties-to-even):
    //   d = p15 - s7 = e' + (3-bmax) - s7
    //   r = rne(mu * 2^min(0,d)) * 2^(max(0,d) - 15)
    {
        const int C = 3 - bmax;
        #pragma unroll
        for (int jj = 0; jj < 2; jj++) {
            int j  = tid + jj * 256;
            int w  = s_ms7[j & 31];
            int d  = (j >> 5) + C - (w >> 8);
            int dn = min(d, 0);
            int dp = d - dn;
            float muf = (float)(w & 255);
            float m2  = rintf(muf * __int_as_float((dn + 127) << 23));
            s_res[j]  = m2 * __int_as_float((dp + 112) << 23);   // * 2^(dp-15)
        }
    }
    __syncthreads();                         // bar4

    // Epilogue: one shared load per element.
    float res[EPT];
    #pragma unroll
    for (int k = 0; k < EPT; k++) res[k] = s_res[pe8[k]];
    *(float4*)(orow)     = make_float4(res[0], res[1], res[2], res[3]);
    *(float4*)(orow + 4) = make_float4(res[4], res[5], res[6], res[7]);
}

extern "C" void kernel_launch(void* const* d_in, const int* in_sizes, int n_in,
                              void* d_out, int out_size)
{
    const float* x = (const float*)d_in[0];
    float* out = (float*)d_out;
    int rows = in_sizes[0] / D_DIM;
    mxint_softmax_kernel<<<rows, TPB>>>(x, out);
}